// round 2
// baseline (speedup 1.0000x reference)
#include <cuda_runtime.h>
#include <stdint.h>

// gcnlayer2: out1 = A1 @ x1 ; out2 = A2 @ x2   (COO SpMM, scatter-atomic)
// N_NODES=65536, D_FEAT=64, N_EDGES=1048576 per matrix.
// Layout: 16 threads per edge, each thread handles one float4 (16B) slice of
// the 64-float feature row. Warp = 2 edges, gathers and reductions are fully
// coalesced 256B segments. Reduction via red.global.add.v4.f32 (no return).

#define DFEAT 64
#define VEC_PER_ROW (DFEAT / 4)   // 16 float4 per feature row

__global__ void zero_kernel(float4* __restrict__ out, int n4) {
    int i = blockIdx.x * blockDim.x + threadIdx.x;
    if (i < n4) out[i] = make_float4(0.f, 0.f, 0.f, 0.f);
}

__global__ void __launch_bounds__(256) spmm_scatter_kernel(
    const int*   __restrict__ a1_rows,
    const int*   __restrict__ a1_cols,
    const float* __restrict__ a1_vals,
    const int*   __restrict__ a2_rows,
    const int*   __restrict__ a2_cols,
    const float* __restrict__ a2_vals,
    const float4* __restrict__ x1,
    const float4* __restrict__ x2,
    float* __restrict__ out1,
    float* __restrict__ out2,
    int n_edges)
{
    int t = blockIdx.x * blockDim.x + threadIdx.x;
    int e = t >> 4;          // edge index across both matrices [0, 2*n_edges)
    int i = t & 15;          // float4 slice within the feature row
    if (e >= 2 * n_edges) return;

    const int*   rows;
    const int*   cols;
    const float* vals;
    const float4* x;
    float* out;
    if (e < n_edges) {
        rows = a1_rows; cols = a1_cols; vals = a1_vals; x = x1; out = out1;
    } else {
        e -= n_edges;
        rows = a2_rows; cols = a2_cols; vals = a2_vals; x = x2; out = out2;
    }

    int   r = __ldg(&rows[e]);
    int   c = __ldg(&cols[e]);
    float v = __ldg(&vals[e]);

    float4 xv = __ldg(&x[(size_t)c * VEC_PER_ROW + i]);
    float4 p;
    p.x = v * xv.x;
    p.y = v * xv.y;
    p.z = v * xv.z;
    p.w = v * xv.w;

    float* dst = out + (size_t)r * DFEAT + i * 4;
    asm volatile("red.global.add.v4.f32 [%0], {%1, %2, %3, %4};"
                 :: "l"(dst), "f"(p.x), "f"(p.y), "f"(p.z), "f"(p.w)
                 : "memory");
}

extern "C" void kernel_launch(void* const* d_in, const int* in_sizes, int n_in,
                              void* d_out, int out_size) {
    const float* x1     = (const float*)d_in[0];
    const float* x2     = (const float*)d_in[1];
    const int*   a1_rows = (const int*)d_in[2];
    const int*   a1_cols = (const int*)d_in[3];
    const float* a1_vals = (const float*)d_in[4];
    const int*   a2_rows = (const int*)d_in[5];
    const int*   a2_cols = (const int*)d_in[6];
    const float* a2_vals = (const float*)d_in[7];

    float* out = (float*)d_out;
    int n_edges = in_sizes[2];                 // 1048576
    int n_nodes = in_sizes[0] / DFEAT;         // 65536
    int half = n_nodes * DFEAT;                // elements in out1

    // Zero the (poisoned) output: out_size floats = out_size/4 float4.
    int n4 = out_size / 4;
    {
        int threads = 256;
        int blocks = (n4 + threads - 1) / threads;
        zero_kernel<<<blocks, threads>>>((float4*)out, n4);
    }

    // One fused scatter over both matrices: 2*E edges, 16 threads each.
    {
        long long total_threads = 2LL * n_edges * VEC_PER_ROW;
        int threads = 256;
        long long blocks = (total_threads + threads - 1) / threads;
        spmm_scatter_kernel<<<(unsigned)blocks, threads>>>(
            a1_rows, a1_cols, a1_vals,
            a2_rows, a2_cols, a2_vals,
            (const float4*)x1, (const float4*)x2,
            out, out + half, n_edges);
    }
}

// round 3
// speedup vs baseline: 1.0019x; 1.0019x over previous
#include <cuda_runtime.h>
#include <stdint.h>

// gcnlayer2: out1 = A1 @ x1 ; out2 = A2 @ x2   (COO SpMM, scatter-atomic)
// N_NODES=65536, D_FEAT=64, N_EDGES=1048576 per matrix.
// Layout: 16 threads per edge, each thread handles one float4 (16B) slice of
// the 64-float feature row. Warp = 2 edges, gathers and reductions are fully
// coalesced 256B segments. Reduction via red.global.add.v4.f32 (no return).

#define DFEAT 64
#define VEC_PER_ROW (DFEAT / 4)   // 16 float4 per feature row

__global__ void zero_kernel(float4* __restrict__ out, int n4) {
    int i = blockIdx.x * blockDim.x + threadIdx.x;
    if (i < n4) out[i] = make_float4(0.f, 0.f, 0.f, 0.f);
}

__global__ void __launch_bounds__(256) spmm_scatter_kernel(
    const int*   __restrict__ a1_rows,
    const int*   __restrict__ a1_cols,
    const float* __restrict__ a1_vals,
    const int*   __restrict__ a2_rows,
    const int*   __restrict__ a2_cols,
    const float* __restrict__ a2_vals,
    const float4* __restrict__ x1,
    const float4* __restrict__ x2,
    float* __restrict__ out1,
    float* __restrict__ out2,
    int n_edges)
{
    int t = blockIdx.x * blockDim.x + threadIdx.x;
    int e = t >> 4;          // edge index across both matrices [0, 2*n_edges)
    int i = t & 15;          // float4 slice within the feature row
    if (e >= 2 * n_edges) return;

    const int*   rows;
    const int*   cols;
    const float* vals;
    const float4* x;
    float* out;
    if (e < n_edges) {
        rows = a1_rows; cols = a1_cols; vals = a1_vals; x = x1; out = out1;
    } else {
        e -= n_edges;
        rows = a2_rows; cols = a2_cols; vals = a2_vals; x = x2; out = out2;
    }

    int   r = __ldg(&rows[e]);
    int   c = __ldg(&cols[e]);
    float v = __ldg(&vals[e]);

    float4 xv = __ldg(&x[(size_t)c * VEC_PER_ROW + i]);
    float4 p;
    p.x = v * xv.x;
    p.y = v * xv.y;
    p.z = v * xv.z;
    p.w = v * xv.w;

    float* dst = out + (size_t)r * DFEAT + i * 4;
    asm volatile("red.global.add.v4.f32 [%0], {%1, %2, %3, %4};"
                 :: "l"(dst), "f"(p.x), "f"(p.y), "f"(p.z), "f"(p.w)
                 : "memory");
}

extern "C" void kernel_launch(void* const* d_in, const int* in_sizes, int n_in,
                              void* d_out, int out_size) {
    const float* x1     = (const float*)d_in[0];
    const float* x2     = (const float*)d_in[1];
    const int*   a1_rows = (const int*)d_in[2];
    const int*   a1_cols = (const int*)d_in[3];
    const float* a1_vals = (const float*)d_in[4];
    const int*   a2_rows = (const int*)d_in[5];
    const int*   a2_cols = (const int*)d_in[6];
    const float* a2_vals = (const float*)d_in[7];

    float* out = (float*)d_out;
    int n_edges = in_sizes[2];                 // 1048576
    int n_nodes = in_sizes[0] / DFEAT;         // 65536
    int half = n_nodes * DFEAT;                // elements in out1

    // Zero the (poisoned) output: out_size floats = out_size/4 float4.
    int n4 = out_size / 4;
    {
        int threads = 256;
        int blocks = (n4 + threads - 1) / threads;
        zero_kernel<<<blocks, threads>>>((float4*)out, n4);
    }

    // One fused scatter over both matrices: 2*E edges, 16 threads each.
    {
        long long total_threads = 2LL * n_edges * VEC_PER_ROW;
        int threads = 256;
        long long blocks = (total_threads + threads - 1) / threads;
        spmm_scatter_kernel<<<(unsigned)blocks, threads>>>(
            a1_rows, a1_cols, a1_vals,
            a2_rows, a2_cols, a2_vals,
            (const float4*)x1, (const float4*)x2,
            out, out + half, n_edges);
    }
}

// round 4
// speedup vs baseline: 1.0028x; 1.0009x over previous
#include <cuda_runtime.h>
#include <stdint.h>

// gcnlayer2: out1 = A1 @ x1 ; out2 = A2 @ x2   (COO SpMM, scatter-atomic)
// N_NODES=65536, D_FEAT=64, N_EDGES=1048576 per matrix.
// Layout: 16 threads per edge, each thread handles one float4 (16B) slice of
// the 64-float feature row. Warp = 2 edges, gathers and reductions are fully
// coalesced 256B segments. Reduction via red.global.add.v4.f32 (no return).

#define DFEAT 64
#define VEC_PER_ROW (DFEAT / 4)   // 16 float4 per feature row

__global__ void zero_kernel(float4* __restrict__ out, int n4) {
    int i = blockIdx.x * blockDim.x + threadIdx.x;
    if (i < n4) out[i] = make_float4(0.f, 0.f, 0.f, 0.f);
}

__global__ void __launch_bounds__(256) spmm_scatter_kernel(
    const int*   __restrict__ a1_rows,
    const int*   __restrict__ a1_cols,
    const float* __restrict__ a1_vals,
    const int*   __restrict__ a2_rows,
    const int*   __restrict__ a2_cols,
    const float* __restrict__ a2_vals,
    const float4* __restrict__ x1,
    const float4* __restrict__ x2,
    float* __restrict__ out1,
    float* __restrict__ out2,
    int n_edges)
{
    int t = blockIdx.x * blockDim.x + threadIdx.x;
    int e = t >> 4;          // edge index across both matrices [0, 2*n_edges)
    int i = t & 15;          // float4 slice within the feature row
    if (e >= 2 * n_edges) return;

    const int*   rows;
    const int*   cols;
    const float* vals;
    const float4* x;
    float* out;
    if (e < n_edges) {
        rows = a1_rows; cols = a1_cols; vals = a1_vals; x = x1; out = out1;
    } else {
        e -= n_edges;
        rows = a2_rows; cols = a2_cols; vals = a2_vals; x = x2; out = out2;
    }

    int   r = __ldg(&rows[e]);
    int   c = __ldg(&cols[e]);
    float v = __ldg(&vals[e]);

    float4 xv = __ldg(&x[(size_t)c * VEC_PER_ROW + i]);
    float4 p;
    p.x = v * xv.x;
    p.y = v * xv.y;
    p.z = v * xv.z;
    p.w = v * xv.w;

    float* dst = out + (size_t)r * DFEAT + i * 4;
    asm volatile("red.global.add.v4.f32 [%0], {%1, %2, %3, %4};"
                 :: "l"(dst), "f"(p.x), "f"(p.y), "f"(p.z), "f"(p.w)
                 : "memory");
}

extern "C" void kernel_launch(void* const* d_in, const int* in_sizes, int n_in,
                              void* d_out, int out_size) {
    const float* x1     = (const float*)d_in[0];
    const float* x2     = (const float*)d_in[1];
    const int*   a1_rows = (const int*)d_in[2];
    const int*   a1_cols = (const int*)d_in[3];
    const float* a1_vals = (const float*)d_in[4];
    const int*   a2_rows = (const int*)d_in[5];
    const int*   a2_cols = (const int*)d_in[6];
    const float* a2_vals = (const float*)d_in[7];

    float* out = (float*)d_out;
    int n_edges = in_sizes[2];                 // 1048576
    int n_nodes = in_sizes[0] / DFEAT;         // 65536
    int half = n_nodes * DFEAT;                // elements in out1

    // Zero the (poisoned) output: out_size floats = out_size/4 float4.
    int n4 = out_size / 4;
    {
        int threads = 256;
        int blocks = (n4 + threads - 1) / threads;
        zero_kernel<<<blocks, threads>>>((float4*)out, n4);
    }

    // One fused scatter over both matrices: 2*E edges, 16 threads each.
    {
        long long total_threads = 2LL * n_edges * VEC_PER_ROW;
        int threads = 256;
        long long blocks = (total_threads + threads - 1) / threads;
        spmm_scatter_kernel<<<(unsigned)blocks, threads>>>(
            a1_rows, a1_cols, a1_vals,
            a2_rows, a2_cols, a2_vals,
            (const float4*)x1, (const float4*)x2,
            out, out + half, n_edges);
    }
}

// round 5
// speedup vs baseline: 1.3409x; 1.3372x over previous
#include <cuda_runtime.h>
#include <stdint.h>

// gcnlayer2: out1 = A1 @ x1 ; out2 = A2 @ x2   (COO SpMM, scatter-atomic)
// N_NODES=65536, D_FEAT=64, N_EDGES=1048576 per matrix.
//
// R5 change vs R0: EPT=4 edge batching per 16-thread group.
//  - Indices for 4 contiguous edges loaded as int4/int4/float4 (3 LDG.128,
//    warp-broadcast) instead of 12 scalar LDGs.
//  - 4 independent x-row gathers per thread -> MLP=4 hides the ~240cyc
//    L2-hit latency that made the R0 kernel latency-bound (issue=38%).
//  - Reductions still red.global.add.v4.f32 (no return trip).

#define DFEAT 64
#define VEC_PER_ROW (DFEAT / 4)   // 16 float4 per feature row
#define EPT 4                     // edges per 16-thread group

__global__ void zero_kernel(float4* __restrict__ out, int n4) {
    int i = blockIdx.x * blockDim.x + threadIdx.x;
    if (i < n4) out[i] = make_float4(0.f, 0.f, 0.f, 0.f);
}

__device__ __forceinline__ void red_add_v4(float* dst, float4 p) {
    asm volatile("red.global.add.v4.f32 [%0], {%1, %2, %3, %4};"
                 :: "l"(dst), "f"(p.x), "f"(p.y), "f"(p.z), "f"(p.w)
                 : "memory");
}

__global__ void __launch_bounds__(256) spmm_scatter_kernel(
    const int4*   __restrict__ a1_rows,
    const int4*   __restrict__ a1_cols,
    const float4* __restrict__ a1_vals,
    const int4*   __restrict__ a2_rows,
    const int4*   __restrict__ a2_cols,
    const float4* __restrict__ a2_vals,
    const float4* __restrict__ x1,
    const float4* __restrict__ x2,
    float* __restrict__ out1,
    float* __restrict__ out2,
    int n_groups)   // n_edges / EPT per matrix
{
    int t = blockIdx.x * blockDim.x + threadIdx.x;
    int g = t >> 4;          // group id across both matrices [0, 2*n_groups)
    int i = t & 15;          // float4 slice within the feature row
    if (g >= 2 * n_groups) return;

    const int4*   rows;
    const int4*   cols;
    const float4* vals;
    const float4* x;
    float* out;
    if (g < n_groups) {
        rows = a1_rows; cols = a1_cols; vals = a1_vals; x = x1; out = out1;
    } else {
        g -= n_groups;
        rows = a2_rows; cols = a2_cols; vals = a2_vals; x = x2; out = out2;
    }

    // 4 contiguous edges' metadata in 3 vector loads (broadcast across lanes).
    int4   r4 = __ldg(&rows[g]);
    int4   c4 = __ldg(&cols[g]);
    float4 v4 = __ldg(&vals[g]);

    // 4 independent gathers -> MLP=4 on the L2-hit latency path.
    float4 xa = __ldg(&x[(size_t)c4.x * VEC_PER_ROW + i]);
    float4 xb = __ldg(&x[(size_t)c4.y * VEC_PER_ROW + i]);
    float4 xc = __ldg(&x[(size_t)c4.z * VEC_PER_ROW + i]);
    float4 xd = __ldg(&x[(size_t)c4.w * VEC_PER_ROW + i]);

    float4 pa = make_float4(v4.x * xa.x, v4.x * xa.y, v4.x * xa.z, v4.x * xa.w);
    float4 pb = make_float4(v4.y * xb.x, v4.y * xb.y, v4.y * xb.z, v4.y * xb.w);
    float4 pc = make_float4(v4.z * xc.x, v4.z * xc.y, v4.z * xc.z, v4.z * xc.w);
    float4 pd = make_float4(v4.w * xd.x, v4.w * xd.y, v4.w * xd.z, v4.w * xd.w);

    int io = i * 4;
    red_add_v4(out + (size_t)r4.x * DFEAT + io, pa);
    red_add_v4(out + (size_t)r4.y * DFEAT + io, pb);
    red_add_v4(out + (size_t)r4.z * DFEAT + io, pc);
    red_add_v4(out + (size_t)r4.w * DFEAT + io, pd);
}

extern "C" void kernel_launch(void* const* d_in, const int* in_sizes, int n_in,
                              void* d_out, int out_size) {
    const float* x1      = (const float*)d_in[0];
    const float* x2      = (const float*)d_in[1];
    const int*   a1_rows = (const int*)d_in[2];
    const int*   a1_cols = (const int*)d_in[3];
    const float* a1_vals = (const float*)d_in[4];
    const int*   a2_rows = (const int*)d_in[5];
    const int*   a2_cols = (const int*)d_in[6];
    const float* a2_vals = (const float*)d_in[7];

    float* out = (float*)d_out;
    int n_edges = in_sizes[2];                 // 1048576
    int n_nodes = in_sizes[0] / DFEAT;         // 65536
    int half = n_nodes * DFEAT;                // elements in out1
    int n_groups = n_edges / EPT;              // 262144 (E divisible by 4)

    // Zero the (poisoned) output.
    int n4 = out_size / 4;
    {
        int threads = 256;
        int blocks = (n4 + threads - 1) / threads;
        zero_kernel<<<blocks, threads>>>((float4*)out, n4);
    }

    // Fused scatter: 2 * n_groups groups, 16 threads each.
    {
        long long total_threads = 2LL * n_groups * VEC_PER_ROW;
        int threads = 256;
        long long blocks = (total_threads + threads - 1) / threads;
        spmm_scatter_kernel<<<(unsigned)blocks, threads>>>(
            (const int4*)a1_rows, (const int4*)a1_cols, (const float4*)a1_vals,
            (const int4*)a2_rows, (const int4*)a2_cols, (const float4*)a2_vals,
            (const float4*)x1, (const float4*)x2,
            out, out + half, n_edges / EPT);
    }
}